// round 10
// baseline (speedup 1.0000x reference)
#include <cuda_runtime.h>
#include <cuda_fp16.h>
#include <mma.h>
#include <math.h>

using namespace nvcuda;

#define N_NODES 100000
#define N_EDGES 1600000
#define F_IN    128
#define F_E     32
#define DH      128   // D*H
#define NH      4     // heads
#define FULLM   0xffffffffu
#define SCAN_BLOCKS 98          // ceil(100000/1024)
#define HIST_BLOCKS 6250        // 6250*256 = 1.6M edges
#define GEMM_TILES  1563        // ceil(100000/64)
#define AGG_NPB     64          // nodes per block in agg_out
#define AGG_BLOCKS  1563        // ceil(100000/64)

// -------- scratch (static device globals; zero-initialized at load) --------
__device__ __half2 g_np_h[(size_t)N_NODES * 64];      // node_proj fp16, 25.6 MB
__device__ float g_ssrc[N_NODES * NH];
__device__ float g_v[NH * F_E];                       // W_edge @ a_edge (per head)
__device__ __half g_Wo_h[DH * 32];                    // W_out in fp16
__device__ int g_cnt[N_NODES];                        // zeroed by prev run's agg_out
__device__ int g_rowptr[N_NODES + 1];
__device__ int g_head[N_NODES];
__device__ unsigned long long g_state[SCAN_BLOCKS];   // zeroed by prev run's agg_out
__device__ float4 g_p4[N_EDGES];                      // attn numerators, dst-sorted
__device__ int    g_src[N_EDGES];                     // src ids, dst-sorted

static __device__ __forceinline__ unsigned sm32(const void* p) {
    return (unsigned)__cvta_generic_to_shared(p);
}

// ===== launch 0: folds — v = We@a_edge, W_out -> fp16 =====
__global__ void __launch_bounds__(256) k_fold(const float* __restrict__ We,
                                              const float* __restrict__ AK,
                                              const float* __restrict__ Wo) {
    int t = threadIdx.x;
    if (t < 128) {
        int h = t >> 5, k = t & 31;
        float s = 0.f;
#pragma unroll
        for (int d = 0; d < 32; d++)
            s += We[k * DH + h * 32 + d] * AK[h * 96 + 64 + d];
        g_v[t] = s;
    }
#pragma unroll
    for (int i = 0; i < 16; i++) {
        int idx = i * 256 + t;
        g_Wo_h[idx] = __float2half_rn(Wo[idx]);
    }
}

// ===== launch 1: hist + node GEMM (wmma, fused ssrc epilogue) =====
__global__ void __launch_bounds__(256) k_front(const float* __restrict__ NF,
                                               const int* __restrict__ EI,
                                               const float* __restrict__ Wn,
                                               const float* __restrict__ AK) {
    __shared__ __align__(16) unsigned char sraw[49152];
    int t = threadIdx.x, b = blockIdx.x;

    if (b < HIST_BLOCKS) {                       // ---- dst histogram ----
        int e = b * 256 + t;
        int2 ei = reinterpret_cast<const int2*>(EI)[e];
        atomicAdd(&g_cnt[ei.y], 1);
        return;
    }

    // ---- GEMM tile: 64 rows of node_proj + ssrc scores ----
    int row0 = (b - HIST_BLOCKS) * 64;
    __half* sW = reinterpret_cast<__half*>(sraw);            // 128x128 = 32 KB
    __half* sA = reinterpret_cast<__half*>(sraw + 32768);    // 64x128  = 16 KB
    float*  sC = reinterpret_cast<float*>(sraw + 32768);     // 64x64 f32 reuse

#pragma unroll
    for (int i = 0; i < 32; i++) {
        int idx = i * 256 + t;
        float2 w2 = reinterpret_cast<const float2*>(Wn)[idx];
        reinterpret_cast<__half2*>(sW)[idx] = __floats2half2_rn(w2.x, w2.y);
    }
#pragma unroll
    for (int i = 0; i < 8; i++) {
        int idx = i * 256 + t;
        int r = idx >> 5, c4 = idx & 31;
        int gr = row0 + r;
        float4 v = (gr < N_NODES)
            ? reinterpret_cast<const float4*>(NF)[(size_t)gr * 32 + c4]
            : make_float4(0.f, 0.f, 0.f, 0.f);
        __half2 h01 = __floats2half2_rn(v.x, v.y);
        __half2 h23 = __floats2half2_rn(v.z, v.w);
        uint2 raw;
        raw.x = *reinterpret_cast<unsigned*>(&h01);
        raw.y = *reinterpret_cast<unsigned*>(&h23);
        reinterpret_cast<uint2*>(sA)[idx] = raw;
    }
    __syncthreads();

    int w = t >> 5, wm = w >> 1, wn = w & 1;
    wmma::fragment<wmma::accumulator, 16, 16, 16, float> c[4];
#pragma unroll
    for (int j = 0; j < 4; j++) wmma::fill_fragment(c[j], 0.f);
#pragma unroll
    for (int k = 0; k < 8; k++) {
        wmma::fragment<wmma::matrix_a, 16, 16, 16, __half, wmma::row_major> a;
        wmma::load_matrix_sync(a, sA + (wm * 16) * 128 + k * 16, 128);
#pragma unroll
        for (int j = 0; j < 4; j++) {
            wmma::fragment<wmma::matrix_b, 16, 16, 16, __half, wmma::row_major> bf;
            wmma::load_matrix_sync(bf, sW + (k * 16) * 128 + wn * 64 + j * 16, 128);
            wmma::mma_sync(c[j], a, bf, c[j]);
        }
    }

#pragma unroll
    for (int jh = 0; jh < 2; jh++) {
        __syncthreads();
        if (wn == jh) {
#pragma unroll
            for (int j = 0; j < 4; j++)
                wmma::store_matrix_sync(sC + (wm * 16) * 64 + j * 16, c[j],
                                        64, wmma::mem_row_major);
        }
        __syncthreads();
#pragma unroll
        for (int i = 0; i < 8; i++) {
            int idx = i * 256 + t;
            int r = idx >> 5, c2 = idx & 31;
            int gr = row0 + r;
            if (gr < N_NODES) {
                float2 v = reinterpret_cast<const float2*>(sC)[r * 32 + c2];
                g_np_h[(size_t)gr * 64 + jh * 32 + c2] = __floats2half2_rn(v.x, v.y);
            }
        }
        if (t < 128) {
            int r = t >> 1, hh = t & 1, h = jh * 2 + hh;
            int gr = row0 + r;
            if (gr < N_NODES) {
                const float4* akp = reinterpret_cast<const float4*>(AK + h * 96);
                const float4* cr = reinterpret_cast<const float4*>(sC + r * 64 + hh * 32);
                float s = 0.f;
#pragma unroll
                for (int k4 = 0; k4 < 8; k4++) {
                    float4 a = cr[k4];
                    float4 ak = akp[k4];
                    s += a.x * ak.x + a.y * ak.y + a.z * ak.z + a.w * ak.w;
                }
                g_ssrc[gr * 4 + h] = s;
            }
        }
    }
}

// ===== launch 2: single-pass decoupled-lookback scan -> rowptr + head =====
__global__ void __launch_bounds__(1024) k_scan() {
    __shared__ int s[1024];
    __shared__ int sprefix;
    int t = threadIdx.x, b = blockIdx.x;
    int i = b * 1024 + t;
    int v = (i < N_NODES) ? g_cnt[i] : 0;
    s[t] = v;
    __syncthreads();
    for (int o = 1; o < 1024; o <<= 1) {
        int u = (t >= o) ? s[t - o] : 0;
        __syncthreads();
        s[t] += u;
        __syncthreads();
    }
    int excl = s[t] - v;
    int total = s[1023];

    if (t == 0) {
        unsigned long long st = ((b == 0 ? 2ull : 1ull) << 32) | (unsigned)total;
        atomicExch(&g_state[b], st);
        if (b == 0) sprefix = 0;
    }
    if (b > 0 && t < 32) {
        int lane = t;
        unsigned running = 0;
        int idx = b - 1;
        while (true) {
            int pi = idx - lane;
            unsigned long long sv_ = (pi >= 0) ? atomicAdd(&g_state[pi], 0ull)
                                               : (2ull << 32);
            int flag = (int)(sv_ >> 32);
            unsigned val = (unsigned)sv_;
            unsigned m2 = __ballot_sync(FULLM, flag == 2);
            unsigned m0 = __ballot_sync(FULLM, flag == 0);
            int f2 = m2 ? (__ffs(m2) - 1) : 32;
            int f0 = m0 ? (__ffs(m0) - 1) : 32;
            if (f2 < f0) {
                unsigned cc = (lane <= f2) ? val : 0;
#pragma unroll
                for (int o = 16; o >= 1; o >>= 1) cc += __shfl_down_sync(FULLM, cc, o);
                if (lane == 0) running += cc;
                break;
            } else if (f0 < 32) {
                unsigned cc = (lane < f0) ? val : 0;
#pragma unroll
                for (int o = 16; o >= 1; o >>= 1) cc += __shfl_down_sync(FULLM, cc, o);
                if (lane == 0) running += cc;
                idx -= f0;
            } else {
                unsigned cc = val;
#pragma unroll
                for (int o = 16; o >= 1; o >>= 1) cc += __shfl_down_sync(FULLM, cc, o);
                if (lane == 0) running += cc;
                idx -= 32;
            }
        }
        if (lane == 0) {
            atomicExch(&g_state[b], (2ull << 32) | (unsigned)(running + total));
            sprefix = (int)running;
        }
    }
    __syncthreads();
    int P = sprefix;
    if (i < N_NODES) {
        int r = excl + P;
        g_rowptr[i] = r;
        g_head[i] = r;
    }
    if (b == 0 && t == 0) g_rowptr[N_NODES] = N_EDGES;
}

// ===== launch 3 (PROFILED): permute via wmma edge-score GEMM =====
// 256 edges/block: s_edge(256x4) = EF_h(256x32) @ V(32x16, 4 cols used)
__global__ void __launch_bounds__(256) k_permute(const int* __restrict__ EI,
                                                 const float* __restrict__ EF) {
    __shared__ __align__(16) unsigned char psm[21504];
    __half* sEFh = reinterpret_cast<__half*>(psm);        // 256x32 fp16 (16 KB)
    float*  sC   = reinterpret_cast<float*>(psm);         // 256x20 f32 (alias, 20 KB)
    __half* sV   = reinterpret_cast<__half*>(psm + 20480);// 32x16 fp16 (1 KB)
    int t = threadIdx.x, w = t >> 5;
    int e0 = blockIdx.x * 256;

    // early: edge endpoints + random ssrc gather (in flight during staging)
    int2 ei = reinterpret_cast<const int2*>(EI)[e0 + t];
    float4 ss4 = *reinterpret_cast<const float4*>(&g_ssrc[ei.x * 4]);

    // build V: B[k][n] = v_n[k] for n<4, else 0
#pragma unroll
    for (int i = 0; i < 2; i++) {
        int idx = i * 256 + t;
        int k = idx >> 4, cn = idx & 15;
        sV[idx] = (cn < 4) ? __float2half_rn(g_v[cn * 32 + k]) : __ushort_as_half(0);
    }
    // stage EF as fp16 (2048 float4 -> 8 per thread)
#pragma unroll
    for (int i = 0; i < 8; i++) {
        int idx = i * 256 + t;
        int el = idx >> 3, c4 = idx & 7;
        float4 v = reinterpret_cast<const float4*>(EF)[(size_t)(e0 + el) * 8 + c4];
        __half2 hа = __floats2half2_rn(v.x, v.y);
        __half2 hb = __floats2half2_rn(v.z, v.w);
        uint2 raw;
        raw.x = *reinterpret_cast<unsigned*>(&hа);
        raw.y = *reinterpret_cast<unsigned*>(&hb);
        *reinterpret_cast<uint2*>(&sEFh[el * 32 + c4 * 4]) = raw;
    }
    __syncthreads();

    // wmma: warp w does M-tiles 2w, 2w+1 (16 edges each), K = 2 steps
    wmma::fragment<wmma::accumulator, 16, 16, 16, float> cf[2];
#pragma unroll
    for (int mi = 0; mi < 2; mi++) {
        int mt = 2 * w + mi;
        wmma::fill_fragment(cf[mi], 0.f);
#pragma unroll
        for (int kk = 0; kk < 2; kk++) {
            wmma::fragment<wmma::matrix_a, 16, 16, 16, __half, wmma::row_major> a;
            wmma::load_matrix_sync(a, sEFh + (mt * 16) * 32 + kk * 16, 32);
            wmma::fragment<wmma::matrix_b, 16, 16, 16, __half, wmma::row_major> bf;
            wmma::load_matrix_sync(bf, sV + (kk * 16) * 16, 16);
            wmma::mma_sync(cf[mi], a, bf, cf[mi]);
        }
    }
    __syncthreads();   // A fully consumed before aliasing writes
#pragma unroll
    for (int mi = 0; mi < 2; mi++)
        wmma::store_matrix_sync(sC + (2 * w + mi) * 16 * 20, cf[mi], 20,
                                wmma::mem_row_major);
    __syncthreads();

    // epilogue: p = exp(ssrc + s_edge), counting-sort scatter by dst
    float4 se = *reinterpret_cast<const float4*>(&sC[t * 20]);
    float4 p;
    p.x = __expf(ss4.x + se.x);
    p.y = __expf(ss4.y + se.y);
    p.z = __expf(ss4.z + se.z);
    p.w = __expf(ss4.w + se.w);
    int pos = atomicAdd(&g_head[ei.y], 1);
    g_p4[pos] = p;
    g_src[pos] = ei.x;
}

// ===== launch 4: gather-aggregate (f32x2 FMA) + wmma out-GEMM + gelu =====
// block = 64 nodes; warp = 8 contiguous nodes; whole warp per edge.
__global__ void __launch_bounds__(256) k_agg_out(const float* __restrict__ bo,
                                                 float* __restrict__ out) {
    __shared__ __align__(16) unsigned char sm[27008];
    float*  s_p   = reinterpret_cast<float*>(sm);            // [2][8][32*4] 8 KB
    int*    s_srb = reinterpret_cast<int*>(sm + 8192);       // [2][8][32]   2 KB
    __half* s_Ah  = reinterpret_cast<__half*>(sm + 10240);   // [64][128]   16 KB
    float*  sD    = reinterpret_cast<float*>(sm);            // alias (epilogue)
    float*  sb    = reinterpret_cast<float*>(sm + 26624);    // 32 floats
    int t = threadIdx.x, lane = t & 31, w = t >> 5;

    // re-zero hist/scan state for the NEXT run
    {
        int zi = blockIdx.x * 256 + t;
        if (zi < N_NODES) g_cnt[zi] = 0;
        if (blockIdx.x == 0 && t < SCAN_BLOCKS) g_state[t] = 0ull;
    }
    if (t < 32) sb[t] = bo[t];

    int n0 = blockIdx.x * AGG_NPB;
    int nw0 = n0 + w * 8;
    int nw1 = min(nw0 + 8, N_NODES);

    if (nw0 < N_NODES) {
        int ebeg = g_rowptr[nw0];
        int eend = g_rowptr[nw1];
        int h = lane >> 3;
        const uint2* np2 = reinterpret_cast<const uint2*>(g_np_h);

        auto issue = [&](int cs) {
            int buf = ((cs - ebeg) >> 5) & 1;
            int j = cs + lane;
            if (j < eend) {
                unsigned ap = sm32(s_p + (buf * 8 + w) * 128 + lane * 4);
                asm volatile("cp.async.ca.shared.global [%0], [%1], 16;"
                             :: "r"(ap), "l"(g_p4 + j));
                unsigned as = sm32(s_srb + (buf * 8 + w) * 32 + lane);
                asm volatile("cp.async.ca.shared.global [%0], [%1], 4;"
                             :: "r"(as), "l"(g_src + j));
            }
            asm volatile("cp.async.commit_group;" ::: "memory");
        };

        if (ebeg < eend) {
            issue(ebeg);
            if (ebeg + 32 < eend) issue(ebeg + 32);
        }

        int j = ebeg;
        for (int n = nw0; n < nw1; n++) {
            int en = g_rowptr[n + 1];
            unsigned long long acc01 = 0ull, acc23 = 0ull;
            float ds = 0.f;

            while (j < en) {
                int cb = ebeg + ((j - ebeg) & ~31);
                int ce = min(cb + 32, eend);
                if (j == cb) {
                    if (cb + 32 < eend) {
                        asm volatile("cp.async.wait_group 1;" ::: "memory");
                    } else {
                        asm volatile("cp.async.wait_group 0;" ::: "memory");
                    }
                    __syncwarp();
                }
                int buf = ((cb - ebeg) >> 5) & 1;
                const float* wp = s_p + (buf * 8 + w) * 128;
                const int* ws = s_srb + (buf * 8 + w) * 32;
                int stop = min(en, ce);
                int q0 = j - cb, q1 = stop - cb;
#pragma unroll 4
                for (int qq = q0; qq < q1; qq++) {
                    int src = ws[qq];
                    float ph = wp[qq * 4 + h];
                    uint2 raw = np2[(size_t)src * 32 + lane];
                    float2 f01 = __half22float2(*reinterpret_cast<__half2*>(&raw.x));
                    float2 f23 = __half22float2(*reinterpret_cast<__half2*>(&raw.y));
                    unsigned long long php, f01p, f23p;
                    asm("mov.b64 %0, {%1, %1};" : "=l"(php) : "f"(ph));
                    asm("mov.b64 %0, {%1, %2};" : "=l"(f01p) : "f"(f01.x), "f"(f01.y));
                    asm("mov.b64 %0, {%1, %2};" : "=l"(f23p) : "f"(f23.x), "f"(f23.y));
                    asm("fma.rn.f32x2 %0, %1, %2, %0;" : "+l"(acc01) : "l"(f01p), "l"(php));
                    asm("fma.rn.f32x2 %0, %1, %2, %0;" : "+l"(acc23) : "l"(f23p), "l"(php));
                    ds += ph;
                }
                j = stop;
                if (stop == ce) {
                    __syncwarp();
                    if (cb + 64 < eend) issue(cb + 64);
                }
            }

            float a0, a1, a2, a3;
            asm("mov.b64 {%0, %1}, %2;" : "=f"(a0), "=f"(a1) : "l"(acc01));
            asm("mov.b64 {%0, %1}, %2;" : "=f"(a2), "=f"(a3) : "l"(acc23));
            float inv = 1.f / (ds + 1e-8f);
            __half2 p0 = __floats2half2_rn(a0 * inv, a1 * inv);
            __half2 p1 = __floats2half2_rn(a2 * inv, a3 * inv);
            uint2 pk;
            pk.x = *reinterpret_cast<unsigned*>(&p0);
            pk.y = *reinterpret_cast<unsigned*>(&p1);
            *reinterpret_cast<uint2*>(&s_Ah[(n - n0) * 128 + lane * 4]) = pk;
        }
    }
    __syncthreads();

    // wmma epilogue: D(64x32) = A(64x128,fp16) @ Wo(128x32,fp16), fp32 acc
    {
        int mt = w & 3, nt = w >> 2;
        wmma::fragment<wmma::accumulator, 16, 16, 16, float> c;
        wmma::fill_fragment(c, 0.f);
#pragma unroll
        for (int kk = 0; kk < 8; kk++) {
            wmma::fragment<wmma::matrix_a, 16, 16, 16, __half, wmma::row_major> a;
            wmma::load_matrix_sync(a, s_Ah + (mt * 16) * 128 + kk * 16, 128);
            wmma::fragment<wmma::matrix_b, 16, 16, 16, __half, wmma::row_major> bf;
            wmma::load_matrix_sync(bf, g_Wo_h + (kk * 16) * 32 + nt * 16, 32);
            wmma::mma_sync(c, a, bf, c);
        }
        __syncthreads();   // s_p readers done before aliasing writes
        wmma::store_matrix_sync(sD + (mt * 16) * 32 + nt * 16, c, 32,
                                wmma::mem_row_major);
    }
    __syncthreads();

    // gelu + coalesced store (512 float4)
#pragma unroll
    for (int i = 0; i < 2; i++) {
        int idx = i * 256 + t;
        int r = idx >> 3, c4 = idx & 7;
        int gn = n0 + r;
        if (gn < N_NODES) {
            float4 v = *reinterpret_cast<const float4*>(&sD[r * 32 + c4 * 4]);
            float4 bb = *reinterpret_cast<const float4*>(&sb[c4 * 4]);
            v.x += bb.x; v.y += bb.y; v.z += bb.z; v.w += bb.w;
            v.x = 0.5f * v.x * (1.f + erff(v.x * 0.70710678118f));
            v.y = 0.5f * v.y * (1.f + erff(v.y * 0.70710678118f));
            v.z = 0.5f * v.z * (1.f + erff(v.z * 0.70710678118f));
            v.w = 0.5f * v.w * (1.f + erff(v.w * 0.70710678118f));
            *reinterpret_cast<float4*>(&out[(size_t)gn * 32 + c4 * 4]) = v;
        }
    }
}

extern "C" void kernel_launch(void* const* d_in, const int* in_sizes, int n_in,
                              void* d_out, int out_size) {
    const float* NF = (const float*)d_in[0];   // node_features (N,128)
    const int*   EI = (const int*)  d_in[1];   // edge_index (E,2)
    const float* EF = (const float*)d_in[2];   // edge_features (E,32)
    const float* Wn = (const float*)d_in[3];   // W_node (128,128)
    const float* We = (const float*)d_in[4];   // W_edge (32,128)
    const float* AK = (const float*)d_in[5];   // attn_kernel (4,96)
    const float* Wo = (const float*)d_in[6];   // W_out (128,32)
    const float* bo = (const float*)d_in[7];   // b_out (32,)
    float* out = (float*)d_out;                // (N,32)

    k_fold<<<1, 256>>>(We, AK, Wo);
    k_front<<<HIST_BLOCKS + GEMM_TILES, 256>>>(NF, EI, Wn, AK);
    k_scan<<<SCAN_BLOCKS, 1024>>>();
    k_permute<<<N_EDGES / 256, 256>>>(EI, EF);   // profiled slot (index 3)
    k_agg_out<<<AGG_BLOCKS, 256>>>(bo, out);
}